// round 15
// baseline (speedup 1.0000x reference)
#include <cuda_runtime.h>
#include <cuda_fp16.h>
#include <cstdint>

#define MDIM 8192
#define NDIM 1024
#define KDIM 1024
#define NDEG 8
#define KROW 7232            // 7 planes (d=1..7)*1024 + 64 pad (bias chunk)
#define NCHUNK 113           // KROW / 64

#define BSCALE 4096.0f
#define BSCALE_INV (1.0f / 4096.0f)

// A: chunk-major [NCHUNK][MDIM][64]; B: row-major [NDIM][KROW] (L2-resident)
__device__ __align__(16) __half g_A[(size_t)NCHUNK * MDIM * 64];   // ~118 MB
__device__ __align__(16) __half g_B[(size_t)NDIM * KROW];          // ~14.8 MB

// ---------------- PTX helpers ----------------
__device__ __forceinline__ uint32_t smem_u32(const void* p) {
    uint32_t a;
    asm("{ .reg .u64 t; cvta.to.shared.u64 t, %1; cvt.u32.u64 %0, t; }"
        : "=r"(a) : "l"(p));
    return a;
}
#define CPASYNC16(dst, src)                                                   \
    asm volatile("cp.async.cg.shared.global [%0], [%1], 16;"                  \
                 :: "r"(dst), "l"(src) : "memory")
#define CP_COMMIT() asm volatile("cp.async.commit_group;" ::: "memory")
#define CP_WAIT1()  asm volatile("cp.async.wait_group 1;" ::: "memory")
#define LDSM4(r0, r1, r2, r3, a)                                              \
    asm volatile("ldmatrix.sync.aligned.m8n8.x4.shared.b16 {%0,%1,%2,%3}, [%4];" \
                 : "=r"(r0), "=r"(r1), "=r"(r2), "=r"(r3) : "r"(a) : "memory")
#define MMA16816(d, a0, a1, a2, a3, b0, b1)                                   \
    asm volatile("mma.sync.aligned.m16n8k16.row.col.f32.f16.f16.f32 "         \
                 "{%0,%1,%2,%3},{%4,%5,%6,%7},{%8,%9},{%0,%1,%2,%3};"         \
                 : "+f"((d)[0]), "+f"((d)[1]), "+f"((d)[2]), "+f"((d)[3])     \
                 : "r"(a0), "r"(a1), "r"(a2), "r"(a3), "r"(b0), "r"(b1))

// ---------------- pass 1a: A planes, vectorized x4 -------------------------
__global__ void prep_a(const float* __restrict__ x) {
    const size_t idx4 = (size_t)blockIdx.x * 256 + threadIdx.x;
    const size_t b = idx4 >> 8;
    const uint32_t i0 = ((uint32_t)idx4 & 255) * 4;
    const float4 xv = *(const float4*)(x + b * 1024 + i0);
    float t[4] = {tanhf(xv.x), tanhf(xv.y), tanhf(xv.z), tanhf(xv.w)};
    float lm2[4] = {2.0f, 2.0f, 2.0f, 2.0f};
    float lm1[4] = {t[0], t[1], t[2], t[3]};
    const uint32_t ic = i0 >> 6;
    const uint32_t pos = i0 & 63;
    {
        __half2 h0 = __floats2half2_rn(t[0], t[1]);
        __half2 h1 = __floats2half2_rn(t[2], t[3]);
        *(uint2*)(g_A + ((size_t)ic * MDIM + b) * 64 + pos) =
            make_uint2(*(uint32_t*)&h0, *(uint32_t*)&h1);
    }
    #pragma unroll
    for (int d = 2; d < NDEG; ++d) {
        float l[4];
        #pragma unroll
        for (int j = 0; j < 4; ++j) {
            l[j] = t[j] * lm1[j] + lm2[j];
            lm2[j] = lm1[j]; lm1[j] = l[j];
        }
        __half2 h0 = __floats2half2_rn(l[0], l[1]);
        __half2 h1 = __floats2half2_rn(l[2], l[3]);
        const size_t chunk = (size_t)(d - 1) * 16 + ic;
        *(uint2*)(g_A + (chunk * MDIM + b) * 64 + pos) =
            make_uint2(*(uint32_t*)&h0, *(uint32_t*)&h1);
    }
    if (i0 < 64) {
        __half2 h0 = __floats2half2_rn(i0 == 0 ? 1.0f : 0.0f, 0.0f);
        __half2 hz = __floats2half2_rn(0.0f, 0.0f);
        *(uint2*)(g_A + ((size_t)112 * MDIM + b) * 64 + i0) =
            make_uint2(*(uint32_t*)&h0, *(uint32_t*)&hz);
    }
}

// ---------------- pass 1b: coalesced transpose prep_b ----------------------
__global__ __launch_bounds__(256) void prep_b(const float* __restrict__ coef) {
    __shared__ __half sm[8][32][36];        // [d][o_local][i_local], padded
    const int tid = threadIdx.x;
    const int o0 = blockIdx.x * 32;
    const int i0 = blockIdx.y * 32;

    #pragma unroll
    for (int p = 0; p < 4; ++p) {
        const int q = p * 256 + tid;
        const int il = q >> 5;
        const int ol = q & 31;
        const float* src = coef + ((size_t)(i0 + il) * 1024 + (o0 + ol)) * 8;
        const float4 v0 = *(const float4*)src;
        const float4 v1 = *(const float4*)(src + 4);
        const float c[8] = {v0.x, v0.y, v0.z, v0.w, v1.x, v1.y, v1.z, v1.w};
        #pragma unroll
        for (int d = 1; d < NDEG; ++d)
            sm[d][ol][il] = __float2half_rn(c[d] * BSCALE);
    }
    __syncthreads();

    const int ol = tid >> 3;
    const int i8 = (tid & 7) * 4;
    __half* row = g_B + (size_t)(o0 + ol) * KROW + i0;
    #pragma unroll
    for (int d = 1; d < NDEG; ++d) {
        const uint2 v = *(const uint2*)&sm[d][ol][i8];
        *(uint2*)(row + (size_t)(d - 1) * 1024 + i8) = v;
    }
}

// ---------------- pass 1c: bias slot + zero pad ----------------------------
__global__ void prep_bias(const float* __restrict__ coef) {
    const int lane = threadIdx.x & 31;
    const int ig = threadIdx.x >> 5;
    const int o = blockIdx.x * 32 + lane;
    float s = 0.0f;
    for (int i = ig; i < KDIM; i += 8)
        s += coef[((size_t)i * 1024 + o) * 8];
    __shared__ float red[8][32];
    __shared__ float bias[32];
    red[ig][lane] = s;
    __syncthreads();
    if (ig == 0) {
        float t = 0.0f;
        #pragma unroll
        for (int j = 0; j < 8; ++j) t += red[j][lane];
        bias[lane] = 2.0f * t * BSCALE;
    }
    __syncthreads();
    const int ol = threadIdx.x >> 3;
    const int j0 = threadIdx.x & 7;
    __half* row = g_B + (size_t)(blockIdx.x * 32 + ol) * KROW + 7168;
    #pragma unroll
    for (int rep = 0; rep < 8; ++rep) {
        const int j = j0 + rep * 8;
        row[j] = __float2half_rn(j == 0 ? bias[ol] : 0.0f);
    }
}

// ---------------- pass 2: single-fp16 mma.sync GEMM, BK=64 -----------------
// Pipeline order (R13-proven): WAIT -> syncthreads -> prefetch -> compute.
// Inner loop: B fragments hoisted per ks-pair (bounded: 16 extra regs).
#define A_O 0
#define B_O 16384
#define STAGE_BYTES 32768
#define NSTAGES 3

__global__ __launch_bounds__(256, 2) void lucas_gemm_mma(float* __restrict__ y) {
    extern __shared__ char smem[];
    const uint32_t sb = smem_u32(smem);
    const int tid = threadIdx.x;
    const int lane = tid & 31;
    const int wid = tid >> 5;
    const int wm = wid & 1;
    const int wn = wid >> 1;
    const int m0 = blockIdx.y << 7;
    const int n0 = blockIdx.x << 7;

    uint32_t dstv[4];
    size_t offAv[4], offBv[4];
    #pragma unroll
    for (int s = 0; s < 4; ++s) {
        const int j = tid + s * 256;
        const int r = j >> 3, c = j & 7;
        dstv[s] = (uint32_t)r * 128 + (uint32_t)((c ^ (r & 7)) * 16);
        offAv[s] = (size_t)(m0 + r) * 64 + c * 8;
        offBv[s] = (size_t)(n0 + r) * KROW + c * 8;
    }
    const size_t ASTRIDE = (size_t)MDIM * 64;

    const int q = lane >> 3;
    const int qha = q >> 1;
    const int qhb = q & 1;
    uint32_t rbyteA[4], rxA[4];
    #pragma unroll
    for (int mt = 0; mt < 4; ++mt) {
        int r = wm * 64 + (q & 1) * 8 + (lane & 7) + mt * 16;
        rbyteA[mt] = (uint32_t)r * 128;
        rxA[mt] = (uint32_t)(r & 7);
    }
    uint32_t rbyteB[2], rxB[2];
    #pragma unroll
    for (int p = 0; p < 2; ++p) {
        int n = wn * 32 + (2 * p + (q >> 1)) * 8 + (lane & 7);
        rbyteB[p] = (uint32_t)n * 128;
        rxB[p] = (uint32_t)(n & 7);
    }

    float acc[4][4][4];
    #pragma unroll
    for (int a = 0; a < 4; ++a)
        #pragma unroll
        for (int b = 0; b < 4; ++b)
            #pragma unroll
            for (int k = 0; k < 4; ++k) acc[a][b][k] = 0.0f;

    #pragma unroll
    for (int s = 0; s < NSTAGES - 1; ++s) {
        const uint32_t st = sb + s * STAGE_BYTES;
        #pragma unroll
        for (int v = 0; v < 4; ++v) {
            CPASYNC16(st + A_O + dstv[v], g_A + offAv[v] + (size_t)s * ASTRIDE);
            CPASYNC16(st + B_O + dstv[v], g_B + offBv[v] + (size_t)s * 64);
        }
        CP_COMMIT();
    }

    #pragma unroll 1
    for (int c = 0; c < NCHUNK; ++c) {
        CP_WAIT1();                  // stage c complete
        __syncthreads();             // all warps done reading stage (c-1)%3

        if (c + NSTAGES - 1 < NCHUNK) {   // safe: behind the barrier
            const uint32_t st = sb + ((c + NSTAGES - 1) % NSTAGES) * STAGE_BYTES;
            const size_t gc = (size_t)(c + NSTAGES - 1);
            #pragma unroll
            for (int v = 0; v < 4; ++v) {
                CPASYNC16(st + A_O + dstv[v], g_A + offAv[v] + gc * ASTRIDE);
                CPASYNC16(st + B_O + dstv[v], g_B + offBv[v] + gc * 64);
            }
            CP_COMMIT();
        } else {
            CP_COMMIT();
        }

        const uint32_t st = sb + (c % NSTAGES) * STAGE_BYTES;
        #pragma unroll
        for (int ks2 = 0; ks2 < 2; ++ks2) {
            uint32_t bf[2][2][4];    // [kw][p][reg] — 16 regs held
            #pragma unroll
            for (int kw = 0; kw < 2; ++kw) {
                const uint32_t ks = ks2 * 2 + kw;
                #pragma unroll
                for (int p = 0; p < 2; ++p) {
                    uint32_t ab = st + B_O + rbyteB[p] +
                                  (uint32_t)(((ks * 2 + qhb) ^ rxB[p]) * 16);
                    LDSM4(bf[kw][p][0], bf[kw][p][1], bf[kw][p][2], bf[kw][p][3], ab);
                }
            }
            #pragma unroll
            for (int kw = 0; kw < 2; ++kw) {
                const uint32_t ks = ks2 * 2 + kw;
                #pragma unroll
                for (int mt = 0; mt < 4; ++mt) {
                    uint32_t aa = st + A_O + rbyteA[mt] +
                                  (uint32_t)(((ks * 2 + qha) ^ rxA[mt]) * 16);
                    uint32_t af[4];
                    LDSM4(af[0], af[1], af[2], af[3], aa);
                    #pragma unroll
                    for (int nt = 0; nt < 4; ++nt) {
                        const int p = nt >> 1, h = (nt & 1) * 2;
                        MMA16816(acc[mt][nt], af[0], af[1], af[2], af[3],
                                 bf[kw][p][h], bf[kw][p][h + 1]);
                    }
                }
            }
        }
    }

    const int er = lane >> 2;
    const int ec = (lane & 3) * 2;
    #pragma unroll
    for (int mt = 0; mt < 4; ++mt) {
        #pragma unroll
        for (int nt = 0; nt < 4; ++nt) {
            const size_t row = (size_t)(m0 + wm * 64 + mt * 16 + er);
            const int cn = n0 + wn * 32 + nt * 8 + ec;
            *(float2*)(y + row * NDIM + cn) =
                make_float2(acc[mt][nt][0] * BSCALE_INV,
                            acc[mt][nt][1] * BSCALE_INV);
            *(float2*)(y + (row + 8) * NDIM + cn) =
                make_float2(acc[mt][nt][2] * BSCALE_INV,
                            acc[mt][nt][3] * BSCALE_INV);
        }
    }
}

// ---------------- launch ----------------
extern "C" void kernel_launch(void* const* d_in, const int* in_sizes, int n_in,
                              void* d_out, int out_size) {
    const float* x    = (const float*)d_in[0];   // [8192, 1024] fp32
    const float* coef = (const float*)d_in[1];   // [1024, 1024, 8] fp32
    float* y          = (float*)d_out;           // [8192, 1024] fp32

    cudaFuncSetAttribute(lucas_gemm_mma,
                         cudaFuncAttributeMaxDynamicSharedMemorySize,
                         NSTAGES * STAGE_BYTES);

    // gemm at 0-based launch index 3 (ncu capture slot).
    dim3 gb(NDIM / 32, KDIM / 32);               // (32, 32)
    prep_b<<<gb, 256>>>(coef);
    prep_a<<<(MDIM * KDIM) / (4 * 256), 256>>>(x);
    prep_bias<<<NDIM / 32, 256>>>(coef);
    dim3 grid(NDIM / 128, MDIM / 128);           // (8, 64)
    lucas_gemm_mma<<<grid, 256, NSTAGES * STAGE_BYTES>>>(y);
}

// round 16
// speedup vs baseline: 1.0088x; 1.0088x over previous
#include <cuda_runtime.h>
#include <cuda_fp16.h>
#include <cstdint>

#define MDIM 8192
#define NDIM 1024
#define KDIM 1024
#define NDEG 8
#define KROW 7232            // 7 planes (d=1..7)*1024 + 64 pad (bias chunk)
#define NCHUNK 113           // KROW / 64

#define BSCALE 4096.0f
#define BSCALE_INV (1.0f / 4096.0f)

// A: chunk-major [NCHUNK][MDIM][64]; B: row-major [NDIM][KROW] (L2-resident)
__device__ __align__(16) __half g_A[(size_t)NCHUNK * MDIM * 64];   // ~118 MB
__device__ __align__(16) __half g_B[(size_t)NDIM * KROW];          // ~14.8 MB

// ---------------- PTX helpers ----------------
__device__ __forceinline__ uint32_t smem_u32(const void* p) {
    uint32_t a;
    asm("{ .reg .u64 t; cvta.to.shared.u64 t, %1; cvt.u32.u64 %0, t; }"
        : "=r"(a) : "l"(p));
    return a;
}
#define CPASYNC16(dst, src)                                                   \
    asm volatile("cp.async.cg.shared.global [%0], [%1], 16;"                  \
                 :: "r"(dst), "l"(src) : "memory")
#define CP_COMMIT() asm volatile("cp.async.commit_group;" ::: "memory")
#define CP_WAIT1()  asm volatile("cp.async.wait_group 1;" ::: "memory")
#define LDSM4(r0, r1, r2, r3, a)                                              \
    asm volatile("ldmatrix.sync.aligned.m8n8.x4.shared.b16 {%0,%1,%2,%3}, [%4];" \
                 : "=r"(r0), "=r"(r1), "=r"(r2), "=r"(r3) : "r"(a) : "memory")
#define MMA16816(d, a0, a1, a2, a3, b0, b1)                                   \
    asm volatile("mma.sync.aligned.m16n8k16.row.col.f32.f16.f16.f32 "         \
                 "{%0,%1,%2,%3},{%4,%5,%6,%7},{%8,%9},{%0,%1,%2,%3};"         \
                 : "+f"((d)[0]), "+f"((d)[1]), "+f"((d)[2]), "+f"((d)[3])     \
                 : "r"(a0), "r"(a1), "r"(a2), "r"(a3), "r"(b0), "r"(b1))

// ---------------- pass 1a: A planes, vectorized x4 -------------------------
__global__ void prep_a(const float* __restrict__ x) {
    const size_t idx4 = (size_t)blockIdx.x * 256 + threadIdx.x;
    const size_t b = idx4 >> 8;
    const uint32_t i0 = ((uint32_t)idx4 & 255) * 4;
    const float4 xv = *(const float4*)(x + b * 1024 + i0);
    float t[4] = {tanhf(xv.x), tanhf(xv.y), tanhf(xv.z), tanhf(xv.w)};
    float lm2[4] = {2.0f, 2.0f, 2.0f, 2.0f};
    float lm1[4] = {t[0], t[1], t[2], t[3]};
    const uint32_t ic = i0 >> 6;
    const uint32_t pos = i0 & 63;
    {
        __half2 h0 = __floats2half2_rn(t[0], t[1]);
        __half2 h1 = __floats2half2_rn(t[2], t[3]);
        *(uint2*)(g_A + ((size_t)ic * MDIM + b) * 64 + pos) =
            make_uint2(*(uint32_t*)&h0, *(uint32_t*)&h1);
    }
    #pragma unroll
    for (int d = 2; d < NDEG; ++d) {
        float l[4];
        #pragma unroll
        for (int j = 0; j < 4; ++j) {
            l[j] = t[j] * lm1[j] + lm2[j];
            lm2[j] = lm1[j]; lm1[j] = l[j];
        }
        __half2 h0 = __floats2half2_rn(l[0], l[1]);
        __half2 h1 = __floats2half2_rn(l[2], l[3]);
        const size_t chunk = (size_t)(d - 1) * 16 + ic;
        *(uint2*)(g_A + (chunk * MDIM + b) * 64 + pos) =
            make_uint2(*(uint32_t*)&h0, *(uint32_t*)&h1);
    }
    if (i0 < 64) {
        __half2 h0 = __floats2half2_rn(i0 == 0 ? 1.0f : 0.0f, 0.0f);
        __half2 hz = __floats2half2_rn(0.0f, 0.0f);
        *(uint2*)(g_A + ((size_t)112 * MDIM + b) * 64 + i0) =
            make_uint2(*(uint32_t*)&h0, *(uint32_t*)&hz);
    }
}

// ---------------- pass 1b: coalesced transpose prep_b ----------------------
__global__ __launch_bounds__(256) void prep_b(const float* __restrict__ coef) {
    __shared__ __half sm[8][32][36];        // [d][o_local][i_local], padded
    const int tid = threadIdx.x;
    const int o0 = blockIdx.x * 32;
    const int i0 = blockIdx.y * 32;

    #pragma unroll
    for (int p = 0; p < 4; ++p) {
        const int q = p * 256 + tid;
        const int il = q >> 5;
        const int ol = q & 31;
        const float* src = coef + ((size_t)(i0 + il) * 1024 + (o0 + ol)) * 8;
        const float4 v0 = *(const float4*)src;
        const float4 v1 = *(const float4*)(src + 4);
        const float c[8] = {v0.x, v0.y, v0.z, v0.w, v1.x, v1.y, v1.z, v1.w};
        #pragma unroll
        for (int d = 1; d < NDEG; ++d)
            sm[d][ol][il] = __float2half_rn(c[d] * BSCALE);
    }
    __syncthreads();

    const int ol = tid >> 3;
    const int i8 = (tid & 7) * 4;
    __half* row = g_B + (size_t)(o0 + ol) * KROW + i0;
    #pragma unroll
    for (int d = 1; d < NDEG; ++d) {
        const uint2 v = *(const uint2*)&sm[d][ol][i8];
        *(uint2*)(row + (size_t)(d - 1) * 1024 + i8) = v;
    }
}

// ---------------- pass 1c: bias slot + zero pad ----------------------------
__global__ void prep_bias(const float* __restrict__ coef) {
    const int lane = threadIdx.x & 31;
    const int ig = threadIdx.x >> 5;
    const int o = blockIdx.x * 32 + lane;
    float s = 0.0f;
    for (int i = ig; i < KDIM; i += 8)
        s += coef[((size_t)i * 1024 + o) * 8];
    __shared__ float red[8][32];
    __shared__ float bias[32];
    red[ig][lane] = s;
    __syncthreads();
    if (ig == 0) {
        float t = 0.0f;
        #pragma unroll
        for (int j = 0; j < 8; ++j) t += red[j][lane];
        bias[lane] = 2.0f * t * BSCALE;
    }
    __syncthreads();
    const int ol = threadIdx.x >> 3;
    const int j0 = threadIdx.x & 7;
    __half* row = g_B + (size_t)(blockIdx.x * 32 + ol) * KROW + 7168;
    #pragma unroll
    for (int rep = 0; rep < 8; ++rep) {
        const int j = j0 + rep * 8;
        row[j] = __float2half_rn(j == 0 ? bias[ol] : 0.0f);
    }
}

// ---------------- pass 2: single-fp16 mma.sync GEMM, BK=64 -----------------
// R13-exact pipeline + per-CTA-parity K-chunk rotation (desync co-resident
// CTAs so their sync/load bursts interleave instead of coinciding).
#define A_O 0
#define B_O 16384
#define STAGE_BYTES 32768
#define NSTAGES 3

__global__ __launch_bounds__(256, 2) void lucas_gemm_mma(float* __restrict__ y) {
    extern __shared__ char smem[];
    const uint32_t sb = smem_u32(smem);
    const int tid = threadIdx.x;
    const int lane = tid & 31;
    const int wid = tid >> 5;
    const int wm = wid & 1;
    const int wn = wid >> 1;
    const int m0 = blockIdx.y << 7;
    const int n0 = blockIdx.x << 7;
    // phase rotation: adjacent bids (same SM under CLC placement) get
    // opposite parity -> staggered chunk schedules
    const int ph = ((blockIdx.x + blockIdx.y) & 1) * 56;

    uint32_t dstv[4];
    size_t offAv[4], offBv[4];
    #pragma unroll
    for (int s = 0; s < 4; ++s) {
        const int j = tid + s * 256;
        const int r = j >> 3, c = j & 7;
        dstv[s] = (uint32_t)r * 128 + (uint32_t)((c ^ (r & 7)) * 16);
        offAv[s] = (size_t)(m0 + r) * 64 + c * 8;
        offBv[s] = (size_t)(n0 + r) * KROW + c * 8;
    }
    const size_t ASTRIDE = (size_t)MDIM * 64;

    const int q = lane >> 3;
    const int qha = q >> 1;
    const int qhb = q & 1;
    uint32_t rbyteA[4], rxA[4];
    #pragma unroll
    for (int mt = 0; mt < 4; ++mt) {
        int r = wm * 64 + (q & 1) * 8 + (lane & 7) + mt * 16;
        rbyteA[mt] = (uint32_t)r * 128;
        rxA[mt] = (uint32_t)(r & 7);
    }
    uint32_t rbyteB[2], rxB[2];
    #pragma unroll
    for (int p = 0; p < 2; ++p) {
        int n = wn * 32 + (2 * p + (q >> 1)) * 8 + (lane & 7);
        rbyteB[p] = (uint32_t)n * 128;
        rxB[p] = (uint32_t)(n & 7);
    }

    float acc[4][4][4];
    #pragma unroll
    for (int a = 0; a < 4; ++a)
        #pragma unroll
        for (int b = 0; b < 4; ++b)
            #pragma unroll
            for (int k = 0; k < 4; ++k) acc[a][b][k] = 0.0f;

    #pragma unroll
    for (int s = 0; s < NSTAGES - 1; ++s) {
        const uint32_t st = sb + s * STAGE_BYTES;
        const size_t pc = (size_t)((s + ph) % NCHUNK);     // rotated chunk
        #pragma unroll
        for (int v = 0; v < 4; ++v) {
            CPASYNC16(st + A_O + dstv[v], g_A + offAv[v] + pc * ASTRIDE);
            CPASYNC16(st + B_O + dstv[v], g_B + offBv[v] + pc * 64);
        }
        CP_COMMIT();
    }

    #pragma unroll 1
    for (int c = 0; c < NCHUNK; ++c) {
        CP_WAIT1();
        __syncthreads();

        if (c + NSTAGES - 1 < NCHUNK) {
            const uint32_t st = sb + ((c + NSTAGES - 1) % NSTAGES) * STAGE_BYTES;
            const size_t pc = (size_t)((c + NSTAGES - 1 + ph) % NCHUNK);
            #pragma unroll
            for (int v = 0; v < 4; ++v) {
                CPASYNC16(st + A_O + dstv[v], g_A + offAv[v] + pc * ASTRIDE);
                CPASYNC16(st + B_O + dstv[v], g_B + offBv[v] + pc * 64);
            }
            CP_COMMIT();
        } else {
            CP_COMMIT();
        }

        const uint32_t st = sb + (c % NSTAGES) * STAGE_BYTES;
        #pragma unroll
        for (int ks = 0; ks < 4; ++ks) {
            uint32_t bf[2][4];
            #pragma unroll
            for (int p = 0; p < 2; ++p) {
                uint32_t ab = st + B_O + rbyteB[p] +
                              (uint32_t)((((uint32_t)(ks * 2 + qhb)) ^ rxB[p]) * 16);
                LDSM4(bf[p][0], bf[p][1], bf[p][2], bf[p][3], ab);
            }
            #pragma unroll
            for (int mt = 0; mt < 4; ++mt) {
                uint32_t aa = st + A_O + rbyteA[mt] +
                              (uint32_t)((((uint32_t)(ks * 2 + qha)) ^ rxA[mt]) * 16);
                uint32_t af[4];
                LDSM4(af[0], af[1], af[2], af[3], aa);
                #pragma unroll
                for (int nt = 0; nt < 4; ++nt) {
                    const int p = nt >> 1, h = (nt & 1) * 2;
                    MMA16816(acc[mt][nt], af[0], af[1], af[2], af[3],
                             bf[p][h], bf[p][h + 1]);
                }
            }
        }
    }

    const int er = lane >> 2;
    const int ec = (lane & 3) * 2;
    #pragma unroll
    for (int mt = 0; mt < 4; ++mt) {
        #pragma unroll
        for (int nt = 0; nt < 4; ++nt) {
            const size_t row = (size_t)(m0 + wm * 64 + mt * 16 + er);
            const int cn = n0 + wn * 32 + nt * 8 + ec;
            *(float2*)(y + row * NDIM + cn) =
                make_float2(acc[mt][nt][0] * BSCALE_INV,
                            acc[mt][nt][1] * BSCALE_INV);
            *(float2*)(y + (row + 8) * NDIM + cn) =
                make_float2(acc[mt][nt][2] * BSCALE_INV,
                            acc[mt][nt][3] * BSCALE_INV);
        }
    }
}

// ---------------- launch ----------------
extern "C" void kernel_launch(void* const* d_in, const int* in_sizes, int n_in,
                              void* d_out, int out_size) {
    const float* x    = (const float*)d_in[0];   // [8192, 1024] fp32
    const float* coef = (const float*)d_in[1];   // [1024, 1024, 8] fp32
    float* y          = (float*)d_out;           // [8192, 1024] fp32

    cudaFuncSetAttribute(lucas_gemm_mma,
                         cudaFuncAttributeMaxDynamicSharedMemorySize,
                         NSTAGES * STAGE_BYTES);

    // gemm at 0-based launch index 3 (ncu capture slot).
    dim3 gb(NDIM / 32, KDIM / 32);               // (32, 32)
    prep_b<<<gb, 256>>>(coef);
    prep_a<<<(MDIM * KDIM) / (4 * 256), 256>>>(x);
    prep_bias<<<NDIM / 32, 256>>>(coef);
    dim3 grid(NDIM / 128, MDIM / 128);           // (8, 64)
    lucas_gemm_mma<<<grid, 256, NSTAGES * STAGE_BYTES>>>(y);
}